// round 1
// baseline (speedup 1.0000x reference)
#include <cuda_runtime.h>

#define NTHREADS 256
#define GRID 148
#define NPAIRS 8192
#define BATCH 16384

// SMEM arena layout. "big" (131072 B) is time-multiplexed:
//   phase gen/conv1 : X (conv1 im2col input)  [k=256][col=128] fp32
//   phase conv1-epi : X2 (conv2 im2col input) [k=256][s2=16]   at big[0..4095]
//   phase conv2-epi : X3 (conv3 im2col input) [k=256][smp=2]   at big[4096..4607]
//   phase conv3     : partials [4][2][32]                      at big[4608..4863]
struct __align__(16) Smem {
    float W1s[256][32];   // [k=c*8+pqr][f]
    float W2s[256][32];
    float W3s[256][32];
    float W0s[8][32];     // [p0q0r0][c]
    float b0[32], b1[32], b2[32], b3[32];
    float fcw[32];
    float fcb;
    float pad0[3];
    float abc[2][3][16];  // [sample][a/b/c][16]
    float big[256 * 128];
};
#define SMEM_BYTES ((int)sizeof(Smem))

__device__ __forceinline__ unsigned long long pk2(float lo, float hi) {
    unsigned long long r;
    asm("mov.b64 %0, {%1, %2};" : "=l"(r) : "f"(lo), "f"(hi));
    return r;
}
__device__ __forceinline__ void fma2(unsigned long long& d, unsigned long long a, unsigned long long b) {
    asm("fma.rn.f32x2 %0, %1, %2, %0;" : "+l"(d) : "l"(a), "l"(b));
}
__device__ __forceinline__ void upk2(unsigned long long v, float& lo, float& hi) {
    asm("mov.b64 {%0, %1}, %2;" : "=f"(lo), "=f"(hi) : "l"(v));
}

__global__ void __launch_bounds__(NTHREADS, 1) ntc_fused_kernel(
    const int* __restrict__ gi, const int* __restrict__ gj, const int* __restrict__ gk,
    const float* __restrict__ A, const float* __restrict__ Bm, const float* __restrict__ Cm,
    const float* __restrict__ W0, const float* __restrict__ b0,
    const float* __restrict__ W1, const float* __restrict__ b1,
    const float* __restrict__ W2, const float* __restrict__ b2,
    const float* __restrict__ W3, const float* __restrict__ b3,
    const float* __restrict__ fcw, const float* __restrict__ fcb,
    float* __restrict__ out)
{
    extern __shared__ __align__(16) unsigned char smem_raw[];
    Smem* s = reinterpret_cast<Smem*>(smem_raw);
    const int tid = threadIdx.x;
    const int warp = tid >> 5, lane = tid & 31;

    // ---- one-time weight staging (transpose to [k][f]) ----
    for (int idx = tid; idx < 8192; idx += NTHREADS) {
        int f = idx >> 8, k = idx & 255;
        s->W1s[k][f] = W1[idx];
        s->W2s[k][f] = W2[idx];
        s->W3s[k][f] = W3[idx];
    }
    if (tid < 256) {               // W0: [c][j] -> [j][c]
        int c = tid >> 3, j = tid & 7;
        s->W0s[j][c] = W0[tid];
    }
    if (tid < 32) {
        s->b0[tid] = b0[tid]; s->b1[tid] = b1[tid];
        s->b2[tid] = b2[tid]; s->b3[tid] = b3[tid];
        s->fcw[tid] = fcw[tid];
        if (tid == 0) s->fcb = fcb[0];
    }
    __syncthreads();

    for (int pair = blockIdx.x; pair < NPAIRS; pair += gridDim.x) {
        // ---- stage a, b, c rows for the 2 samples ----
        if (tid < 96) {
            int smp = tid / 48, rem = tid % 48, which = rem >> 4, e = rem & 15;
            int sg = 2 * pair + smp;
            const float* src = (which == 0) ? (A + gi[sg] * 16)
                             : (which == 1) ? (Bm + gj[sg] * 16)
                                            : (Cm + gk[sg] * 16);
            s->abc[smp][which][e] = src[e];
        }
        __syncthreads();

        // ---- gen: fused outer-product + conv0 + bias + relu -> X (im2col for conv1)
        // warp = channel group (4 ch), lane = spatial pair s=(2*lane, 2*lane+1)
        {
            int d1 = lane >> 3;
            int h1 = (lane >> 1) & 3;
            int w1a = (lane & 1) << 1;
            unsigned long long wd[4][8];
            #pragma unroll
            for (int cc = 0; cc < 4; ++cc) {
                int c = warp * 4 + cc;
                #pragma unroll
                for (int j = 0; j < 8; ++j) { float w = s->W0s[j][c]; wd[cc][j] = pk2(w, w); }
            }
            #pragma unroll
            for (int smp = 0; smp < 2; ++smp) {
                const float* sa = s->abc[smp][0];
                const float* sb = s->abc[smp][1];
                const float* sc = s->abc[smp][2];
                float a4[4], b4[4], c8[8];
                #pragma unroll
                for (int x = 0; x < 4; ++x) { a4[x] = sa[4 * d1 + x]; b4[x] = sb[4 * h1 + x]; }
                #pragma unroll
                for (int x = 0; x < 8; ++x) c8[x] = sc[4 * w1a + x];
                float ab[16];
                #pragma unroll
                for (int x = 0; x < 4; ++x)
                    #pragma unroll
                    for (int y = 0; y < 4; ++y) ab[x * 4 + y] = a4[x] * b4[y];

                #pragma unroll
                for (int pqr = 0; pqr < 8; ++pqr) {
                    int p = (pqr >> 2) & 1, q = (pqr >> 1) & 1, r = pqr & 1;
                    unsigned long long t2[8];
                    #pragma unroll
                    for (int j = 0; j < 8; ++j) {
                        int p0 = (j >> 2) & 1, q0 = (j >> 1) & 1, r0 = j & 1;
                        float abv = ab[(2 * p + p0) * 4 + (2 * q + q0)];
                        t2[j] = pk2(abv * c8[2 * r + r0], abv * c8[4 + 2 * r + r0]);
                    }
                    #pragma unroll
                    for (int cc = 0; cc < 4; ++cc) {
                        int c = warp * 4 + cc;
                        float bias = s->b0[c];
                        unsigned long long acc = pk2(bias, bias);
                        #pragma unroll
                        for (int j = 0; j < 8; ++j) fma2(acc, wd[cc][j], t2[j]);
                        float vlo, vhi; upk2(acc, vlo, vhi);
                        vlo = fmaxf(vlo, 0.f); vhi = fmaxf(vhi, 0.f);
                        int row = c * 8 + pqr;
                        *reinterpret_cast<float2*>(&s->big[row * 128 + smp * 64 + 2 * lane])
                            = make_float2(vlo, vhi);
                    }
                }
            }
        }
        __syncthreads();

        // ---- conv1: GEMM D[32f x 128s] = W1s[256k x 32f]^T @ X[256k x 128s]
        // thread tile 4f x 4s, accumulators packed f32x2 over filter pairs
        unsigned long long acc1[8];
        const int f0 = (tid & 7) * 4;
        const int s0 = (tid >> 3) * 4;
        {
            #pragma unroll
            for (int u = 0; u < 8; ++u) acc1[u] = 0ULL;
            #pragma unroll 4
            for (int k = 0; k < 256; ++k) {
                float4 wv = *reinterpret_cast<const float4*>(&s->W1s[k][f0]);
                float4 xv = *reinterpret_cast<const float4*>(&s->big[k * 128 + s0]);
                unsigned long long w01 = pk2(wv.x, wv.y);
                unsigned long long w23 = pk2(wv.z, wv.w);
                unsigned long long x0 = pk2(xv.x, xv.x);
                unsigned long long x1 = pk2(xv.y, xv.y);
                unsigned long long x2 = pk2(xv.z, xv.z);
                unsigned long long x3 = pk2(xv.w, xv.w);
                fma2(acc1[0], w01, x0); fma2(acc1[1], w01, x1);
                fma2(acc1[2], w01, x2); fma2(acc1[3], w01, x3);
                fma2(acc1[4], w23, x0); fma2(acc1[5], w23, x1);
                fma2(acc1[6], w23, x2); fma2(acc1[7], w23, x3);
            }
        }
        __syncthreads();   // all X reads done; "big" may now be reused as X2

        // conv1 epilogue: bias + relu, scatter into conv2 im2col layout X2 (big[0..4095])
        {
            #pragma unroll
            for (int fp = 0; fp < 2; ++fp)
                #pragma unroll
                for (int sj = 0; sj < 4; ++sj) {
                    float v0, v1; upk2(acc1[fp * 4 + sj], v0, v1);
                    int fe = f0 + fp * 2, fo = fe + 1;
                    int scol = s0 + sj;
                    int smp = scol >> 6, rem = scol & 63;
                    int d1 = rem >> 4, h1 = (rem >> 2) & 3, w1 = rem & 3;
                    int pqr2 = ((d1 & 1) << 2) | ((h1 & 1) << 1) | (w1 & 1);
                    int s2 = smp * 8 + (((d1 >> 1) << 2) | ((h1 >> 1) << 1) | (w1 >> 1));
                    float ve = fmaxf(v0 + s->b1[fe], 0.f);
                    float vo = fmaxf(v1 + s->b1[fo], 0.f);
                    s->big[(fe * 8 + pqr2) * 16 + s2] = ve;
                    s->big[(fo * 8 + pqr2) * 16 + s2] = vo;
                }
        }
        __syncthreads();

        // ---- conv2: GEMM 32f x 16s2 x 256k, f32x2 packed over s2 pairs ----
        {
            const int f = tid & 31, sp2 = tid >> 5;   // sp2 in 0..7
            unsigned long long acc = 0ULL;
            #pragma unroll 4
            for (int k = 0; k < 256; ++k) {
                float w = s->W2s[k][f];
                float2 x = *reinterpret_cast<const float2*>(&s->big[k * 16 + sp2 * 2]);
                fma2(acc, pk2(w, w), pk2(x.x, x.y));
            }
            float v0, v1; upk2(acc, v0, v1);
            int s2a = sp2 * 2, s2b = s2a + 1;
            float va = fmaxf(v0 + s->b2[f], 0.f);
            float vb = fmaxf(v1 + s->b2[f], 0.f);
            // X3 at big[4096..4607] — disjoint from X2, no sync needed before write
            s->big[4096 + (f * 8 + (s2a & 7)) * 2 + (s2a >> 3)] = va;
            s->big[4096 + (f * 8 + (s2b & 7)) * 2 + (s2b >> 3)] = vb;
        }
        __syncthreads();

        // ---- conv3: K-split partials (4 chunks of 64) ----
        {
            const int f = tid & 31, smp = (tid >> 5) & 1, kc = tid >> 6;
            float acc = 0.f;
            const int kbase = kc * 64;
            #pragma unroll 4
            for (int kk = 0; kk < 64; ++kk) {
                int k = kbase + kk;
                acc += s->W3s[k][f] * s->big[4096 + k * 2 + smp];
            }
            s->big[4608 + kc * 64 + smp * 32 + f] = acc;
        }
        __syncthreads();

        // ---- reduce partials + bias + relu + FC + sigmoid ----
        if (tid < 64) {
            const int f = tid & 31, smp = tid >> 5;
            float v = s->big[4608 +       smp * 32 + f]
                    + s->big[4608 +  64 + smp * 32 + f]
                    + s->big[4608 + 128 + smp * 32 + f]
                    + s->big[4608 + 192 + smp * 32 + f];
            v = fmaxf(v + s->b3[f], 0.f);
            v *= s->fcw[f];
            #pragma unroll
            for (int off = 16; off; off >>= 1) v += __shfl_xor_sync(0xffffffffu, v, off);
            if (f == 0) {
                float r = v + s->fcb;
                out[2 * pair + smp] = 1.f / (1.f + expf(-r));
            }
        }
        __syncthreads();   // protect arena before next iteration's gen writes
    }
}

extern "C" void kernel_launch(void* const* d_in, const int* in_sizes, int n_in,
                              void* d_out, int out_size) {
    const int*   gi  = (const int*)d_in[0];
    const int*   gj  = (const int*)d_in[1];
    const int*   gk  = (const int*)d_in[2];
    const float* A   = (const float*)d_in[3];
    const float* Bm  = (const float*)d_in[4];
    const float* Cm  = (const float*)d_in[5];
    const float* W0  = (const float*)d_in[6];
    const float* b0  = (const float*)d_in[7];
    const float* W1  = (const float*)d_in[8];
    const float* b1  = (const float*)d_in[9];
    const float* W2  = (const float*)d_in[10];
    const float* b2  = (const float*)d_in[11];
    const float* W3  = (const float*)d_in[12];
    const float* b3  = (const float*)d_in[13];
    const float* fcw = (const float*)d_in[14];
    const float* fcb = (const float*)d_in[15];
    float* out = (float*)d_out;

    cudaFuncSetAttribute(ntc_fused_kernel,
                         cudaFuncAttributeMaxDynamicSharedMemorySize, SMEM_BYTES);

    ntc_fused_kernel<<<GRID, NTHREADS, SMEM_BYTES>>>(
        gi, gj, gk, A, Bm, Cm, W0, b0, W1, b1, W2, b2, W3, b3, fcw, fcb, out);
}

// round 3
// speedup vs baseline: 1.0016x; 1.0016x over previous
#include <cuda_runtime.h>

#define NTHREADS 256
#define GRID 148
#define NPAIRS 8192
#define BATCH 16384

// SMEM arena layout. "big" (131072 B) is time-multiplexed:
//   phase gen/conv1 : X (conv1 im2col input)  [k=256][col=128] fp32
//   phase conv1-epi : X2 (conv2 im2col input) [k=256][s2=16]   at big[0..4095]
//   phase conv2-epi : X3 (conv3 im2col input) [k=256][smp=2]   at big[4096..4607]
//   phase conv3     : partials [4][2][32]                      at big[4608..4863]
struct __align__(16) Smem {
    float W1s[256][32];   // [k=c*8+pqr][f]
    float W2s[256][32];
    float W3s[256][32];
    float W0s[8][32];     // [p0q0r0][c]
    float b0[32], b1[32], b2[32], b3[32];
    float fcw[32];
    float fcb;
    float pad0[3];
    float abc[2][3][16];  // [sample][a/b/c][16]
    float big[256 * 128];
};
#define SMEM_BYTES ((int)sizeof(Smem))

__device__ __forceinline__ unsigned long long pk2(float lo, float hi) {
    unsigned long long r;
    asm("mov.b64 %0, {%1, %2};" : "=l"(r) : "f"(lo), "f"(hi));
    return r;
}
__device__ __forceinline__ void fma2(unsigned long long& d, unsigned long long a, unsigned long long b) {
    asm("fma.rn.f32x2 %0, %1, %2, %0;" : "+l"(d) : "l"(a), "l"(b));
}
__device__ __forceinline__ void upk2(unsigned long long v, float& lo, float& hi) {
    asm("mov.b64 {%0, %1}, %2;" : "=f"(lo), "=f"(hi) : "l"(v));
}

__global__ void __launch_bounds__(NTHREADS, 1) ntc_fused_kernel(
    const int* __restrict__ gi, const int* __restrict__ gj, const int* __restrict__ gk,
    const float* __restrict__ A, const float* __restrict__ Bm, const float* __restrict__ Cm,
    const float* __restrict__ W0, const float* __restrict__ b0,
    const float* __restrict__ W1, const float* __restrict__ b1,
    const float* __restrict__ W2, const float* __restrict__ b2,
    const float* __restrict__ W3, const float* __restrict__ b3,
    const float* __restrict__ fcw, const float* __restrict__ fcb,
    float* __restrict__ out)
{
    extern __shared__ __align__(16) unsigned char smem_raw[];
    Smem* s = reinterpret_cast<Smem*>(smem_raw);
    const int tid = threadIdx.x;
    const int warp = tid >> 5, lane = tid & 31;

    // ---- one-time weight staging (transpose to [k][f]) ----
    for (int idx = tid; idx < 8192; idx += NTHREADS) {
        int f = idx >> 8, k = idx & 255;
        s->W1s[k][f] = W1[idx];
        s->W2s[k][f] = W2[idx];
        s->W3s[k][f] = W3[idx];
    }
    if (tid < 256) {               // W0: [c][j] -> [j][c]
        int c = tid >> 3, j = tid & 7;
        s->W0s[j][c] = W0[tid];
    }
    if (tid < 32) {
        s->b0[tid] = b0[tid]; s->b1[tid] = b1[tid];
        s->b2[tid] = b2[tid]; s->b3[tid] = b3[tid];
        s->fcw[tid] = fcw[tid];
        if (tid == 0) s->fcb = fcb[0];
    }
    __syncthreads();

    for (int pair = blockIdx.x; pair < NPAIRS; pair += gridDim.x) {
        // ---- stage a, b, c rows for the 2 samples ----
        if (tid < 96) {
            int smp = tid / 48, rem = tid % 48, which = rem >> 4, e = rem & 15;
            int sg = 2 * pair + smp;
            const float* src = (which == 0) ? (A + gi[sg] * 16)
                             : (which == 1) ? (Bm + gj[sg] * 16)
                                            : (Cm + gk[sg] * 16);
            s->abc[smp][which][e] = src[e];
        }
        __syncthreads();

        // ---- gen: fused outer-product + conv0 + bias + relu -> X (im2col for conv1)
        // warp = channel group (4 ch), lane = spatial pair s=(2*lane, 2*lane+1)
        {
            int d1 = lane >> 3;
            int h1 = (lane >> 1) & 3;
            int w1a = (lane & 1) << 1;
            unsigned long long wd[4][8];
            #pragma unroll
            for (int cc = 0; cc < 4; ++cc) {
                int c = warp * 4 + cc;
                #pragma unroll
                for (int j = 0; j < 8; ++j) { float w = s->W0s[j][c]; wd[cc][j] = pk2(w, w); }
            }
            #pragma unroll
            for (int smp = 0; smp < 2; ++smp) {
                const float* sa = s->abc[smp][0];
                const float* sb = s->abc[smp][1];
                const float* sc = s->abc[smp][2];
                float a4[4], b4[4], c8[8];
                #pragma unroll
                for (int x = 0; x < 4; ++x) { a4[x] = sa[4 * d1 + x]; b4[x] = sb[4 * h1 + x]; }
                #pragma unroll
                for (int x = 0; x < 8; ++x) c8[x] = sc[4 * w1a + x];
                float ab[16];
                #pragma unroll
                for (int x = 0; x < 4; ++x)
                    #pragma unroll
                    for (int y = 0; y < 4; ++y) ab[x * 4 + y] = a4[x] * b4[y];

                #pragma unroll
                for (int pqr = 0; pqr < 8; ++pqr) {
                    int p = (pqr >> 2) & 1, q = (pqr >> 1) & 1, r = pqr & 1;
                    unsigned long long t2[8];
                    #pragma unroll
                    for (int j = 0; j < 8; ++j) {
                        int p0 = (j >> 2) & 1, q0 = (j >> 1) & 1, r0 = j & 1;
                        float abv = ab[(2 * p + p0) * 4 + (2 * q + q0)];
                        t2[j] = pk2(abv * c8[2 * r + r0], abv * c8[4 + 2 * r + r0]);
                    }
                    #pragma unroll
                    for (int cc = 0; cc < 4; ++cc) {
                        int c = warp * 4 + cc;
                        float bias = s->b0[c];
                        unsigned long long acc = pk2(bias, bias);
                        #pragma unroll
                        for (int j = 0; j < 8; ++j) fma2(acc, wd[cc][j], t2[j]);
                        float vlo, vhi; upk2(acc, vlo, vhi);
                        vlo = fmaxf(vlo, 0.f); vhi = fmaxf(vhi, 0.f);
                        int row = c * 8 + pqr;
                        *reinterpret_cast<float2*>(&s->big[row * 128 + smp * 64 + 2 * lane])
                            = make_float2(vlo, vhi);
                    }
                }
            }
        }
        __syncthreads();

        // ---- conv1: GEMM D[32f x 128s] = W1s[256k x 32f]^T @ X[256k x 128s]
        // thread tile 4f x 4s, accumulators packed f32x2 over filter pairs
        unsigned long long acc1[8];
        const int f0 = (tid & 7) * 4;
        const int s0 = (tid >> 3) * 4;
        {
            #pragma unroll
            for (int u = 0; u < 8; ++u) acc1[u] = 0ULL;
            #pragma unroll 4
            for (int k = 0; k < 256; ++k) {
                float4 wv = *reinterpret_cast<const float4*>(&s->W1s[k][f0]);
                float4 xv = *reinterpret_cast<const float4*>(&s->big[k * 128 + s0]);
                unsigned long long w01 = pk2(wv.x, wv.y);
                unsigned long long w23 = pk2(wv.z, wv.w);
                unsigned long long x0 = pk2(xv.x, xv.x);
                unsigned long long x1 = pk2(xv.y, xv.y);
                unsigned long long x2 = pk2(xv.z, xv.z);
                unsigned long long x3 = pk2(xv.w, xv.w);
                fma2(acc1[0], w01, x0); fma2(acc1[1], w01, x1);
                fma2(acc1[2], w01, x2); fma2(acc1[3], w01, x3);
                fma2(acc1[4], w23, x0); fma2(acc1[5], w23, x1);
                fma2(acc1[6], w23, x2); fma2(acc1[7], w23, x3);
            }
        }
        __syncthreads();   // all X reads done; "big" may now be reused as X2

        // conv1 epilogue: bias + relu, scatter into conv2 im2col layout X2 (big[0..4095])
        {
            #pragma unroll
            for (int fp = 0; fp < 2; ++fp)
                #pragma unroll
                for (int sj = 0; sj < 4; ++sj) {
                    float v0, v1; upk2(acc1[fp * 4 + sj], v0, v1);
                    int fe = f0 + fp * 2, fo = fe + 1;
                    int scol = s0 + sj;
                    int smp = scol >> 6, rem = scol & 63;
                    int d1 = rem >> 4, h1 = (rem >> 2) & 3, w1 = rem & 3;
                    int pqr2 = ((d1 & 1) << 2) | ((h1 & 1) << 1) | (w1 & 1);
                    int s2 = smp * 8 + (((d1 >> 1) << 2) | ((h1 >> 1) << 1) | (w1 >> 1));
                    float ve = fmaxf(v0 + s->b1[fe], 0.f);
                    float vo = fmaxf(v1 + s->b1[fo], 0.f);
                    s->big[(fe * 8 + pqr2) * 16 + s2] = ve;
                    s->big[(fo * 8 + pqr2) * 16 + s2] = vo;
                }
        }
        __syncthreads();

        // ---- conv2: GEMM 32f x 16s2 x 256k, f32x2 packed over s2 pairs ----
        {
            const int f = tid & 31, sp2 = tid >> 5;   // sp2 in 0..7
            unsigned long long acc = 0ULL;
            #pragma unroll 4
            for (int k = 0; k < 256; ++k) {
                float w = s->W2s[k][f];
                float2 x = *reinterpret_cast<const float2*>(&s->big[k * 16 + sp2 * 2]);
                fma2(acc, pk2(w, w), pk2(x.x, x.y));
            }
            float v0, v1; upk2(acc, v0, v1);
            int s2a = sp2 * 2, s2b = s2a + 1;
            float va = fmaxf(v0 + s->b2[f], 0.f);
            float vb = fmaxf(v1 + s->b2[f], 0.f);
            // X3 at big[4096..4607] — disjoint from X2, no sync needed before write
            s->big[4096 + (f * 8 + (s2a & 7)) * 2 + (s2a >> 3)] = va;
            s->big[4096 + (f * 8 + (s2b & 7)) * 2 + (s2b >> 3)] = vb;
        }
        __syncthreads();

        // ---- conv3: K-split partials (4 chunks of 64) ----
        {
            const int f = tid & 31, smp = (tid >> 5) & 1, kc = tid >> 6;
            float acc = 0.f;
            const int kbase = kc * 64;
            #pragma unroll 4
            for (int kk = 0; kk < 64; ++kk) {
                int k = kbase + kk;
                acc += s->W3s[k][f] * s->big[4096 + k * 2 + smp];
            }
            s->big[4608 + kc * 64 + smp * 32 + f] = acc;
        }
        __syncthreads();

        // ---- reduce partials + bias + relu + FC + sigmoid ----
        if (tid < 64) {
            const int f = tid & 31, smp = tid >> 5;
            float v = s->big[4608 +       smp * 32 + f]
                    + s->big[4608 +  64 + smp * 32 + f]
                    + s->big[4608 + 128 + smp * 32 + f]
                    + s->big[4608 + 192 + smp * 32 + f];
            v = fmaxf(v + s->b3[f], 0.f);
            v *= s->fcw[f];
            #pragma unroll
            for (int off = 16; off; off >>= 1) v += __shfl_xor_sync(0xffffffffu, v, off);
            if (f == 0) {
                float r = v + s->fcb;
                out[2 * pair + smp] = 1.f / (1.f + expf(-r));
            }
        }
        __syncthreads();   // protect arena before next iteration's gen writes
    }
}

extern "C" void kernel_launch(void* const* d_in, const int* in_sizes, int n_in,
                              void* d_out, int out_size) {
    const int*   gi  = (const int*)d_in[0];
    const int*   gj  = (const int*)d_in[1];
    const int*   gk  = (const int*)d_in[2];
    const float* A   = (const float*)d_in[3];
    const float* Bm  = (const float*)d_in[4];
    const float* Cm  = (const float*)d_in[5];
    const float* W0  = (const float*)d_in[6];
    const float* b0  = (const float*)d_in[7];
    const float* W1  = (const float*)d_in[8];
    const float* b1  = (const float*)d_in[9];
    const float* W2  = (const float*)d_in[10];
    const float* b2  = (const float*)d_in[11];
    const float* W3  = (const float*)d_in[12];
    const float* b3  = (const float*)d_in[13];
    const float* fcw = (const float*)d_in[14];
    const float* fcb = (const float*)d_in[15];
    float* out = (float*)d_out;

    cudaFuncSetAttribute(ntc_fused_kernel,
                         cudaFuncAttributeMaxDynamicSharedMemorySize, SMEM_BYTES);

    ntc_fused_kernel<<<GRID, NTHREADS, SMEM_BYTES>>>(
        gi, gj, gk, A, Bm, Cm, W0, b0, W1, b1, W2, b2, W3, b3, fcw, fcb, out);
}